// round 7
// baseline (speedup 1.0000x reference)
#include <cuda_runtime.h>

// TrigoLinear: out[b,o] = sum_i sin(x[b,i]*w_sin[o,i] + b_sin[o,i]) * w_out[o,i] + b_out[o]
// ALL-POLY: packed f32x2 degree-5 Taylor, w_out folded into Horner form.
// acc += (t*wo) * (1 + tt*(c3 + c5*tt)),  6 packed fma-ops per 2 elements, zero MUFU.

#define B_DIM   1024
#define IN_DIM  512
#define OUT_DIM 512

#define BM 64
#define BN 64
#define BK 32
#define PAD  68    // o-side row stride (floats)
#define PAD2 132   // duplicated-x row stride (floats)

typedef unsigned long long ull;

struct U2 { ull lo, hi; };
union F4U { float4 f; U2 u; };
union F2U { float2 f; ull u; };

__device__ __forceinline__ ull fma2_(ull a, ull b, ull c) {
    ull d; asm("fma.rn.f32x2 %0, %1, %2, %3;" : "=l"(d) : "l"(a), "l"(b), "l"(c)); return d;
}
__device__ __forceinline__ ull mul2_(ull a, ull b) {
    ull d; asm("mul.rn.f32x2 %0, %1, %2;" : "=l"(d) : "l"(a), "l"(b)); return d;
}
__device__ __forceinline__ ull pkc(float c) {
    F2U t; t.f = make_float2(c, c); return t.u;
}

__global__ __launch_bounds__(256, 1)
void trigo_kernel(const float* __restrict__ x,
                  const float* __restrict__ weight,
                  const float* __restrict__ bias,
                  float* __restrict__ out) {
    __shared__ __align__(16) float sx2[BK * PAD2];  // [k][b] duplicated {x,x}
    __shared__ __align__(16) float sws[BK * PAD];   // [k][o] w_sin
    __shared__ __align__(16) float sbs[BK * PAD];   // [k][o] b_sin
    __shared__ __align__(16) float swo[BK * PAD];   // [k][o] w_out

    const int tid = threadIdx.x;
    const int tx = tid & 15;   // 4 outs/thread: o = tx*4 (2 packed pairs)
    const int ty = tid >> 4;   // 4 rows/thread: b = ty*4
    const int bRow = blockIdx.y * BM;
    const int oCol = blockIdx.x * BN;

    const float2* __restrict__ w2 = (const float2*)weight;

    // register staging (software pipeline over LDG)
    float  rx[8];
    float2 rw[8];
    float  rb[8];

    // ---- prologue: tile 0 ----
    #pragma unroll
    for (int j = 0; j < 8; j++) {
        int idx = tid + j * 256;
        int r = idx >> 5, k = idx & 31;
        rx[j] = x[(bRow + r) * IN_DIM + k];
        rw[j] = w2[(oCol + r) * IN_DIM + k];
        rb[j] = bias[(oCol + r) * (IN_DIM + 1) + k];
    }
    #pragma unroll
    for (int j = 0; j < 8; j++) {
        int idx = tid + j * 256;
        int r = idx >> 5, k = idx & 31;
        *(float2*)&sx2[k * PAD2 + r * 2] = make_float2(rx[j], rx[j]);
        swo[k * PAD + r] = rw[j].x;
        sws[k * PAD + r] = rw[j].y;
        sbs[k * PAD + r] = rb[j];
    }
    __syncthreads();

    const ull C3  = pkc(-1.6666667e-1f);
    const ull C5  = pkc( 8.3333333e-3f);
    const ull ONE = pkc(1.0f);

    ull acc[4][2];  // [bb][oo-pair]
    #pragma unroll
    for (int bb = 0; bb < 4; bb++) { acc[bb][0] = 0ull; acc[bb][1] = 0ull; }

    for (int k0 = 0; k0 < IN_DIM; k0 += BK) {
        if (k0 + BK < IN_DIM) {
            #pragma unroll
            for (int j = 0; j < 8; j++) {
                int idx = tid + j * 256;
                int r = idx >> 5, k = idx & 31;
                rx[j] = x[(bRow + r) * IN_DIM + k0 + BK + k];
                rw[j] = w2[(oCol + r) * IN_DIM + k0 + BK + k];
                rb[j] = bias[(oCol + r) * (IN_DIM + 1) + k0 + BK + k];
            }
        }

        #pragma unroll 4
        for (int k = 0; k < BK; k++) {
            // float4 loads give two packed f32x2 operands each (aligned reg pairs)
            F4U ws; ws.f = *(const float4*)&sws[k * PAD + tx * 4];
            F4U bs; bs.f = *(const float4*)&sbs[k * PAD + tx * 4];
            F4U wo; wo.f = *(const float4*)&swo[k * PAD + tx * 4];

            #pragma unroll
            for (int bb = 0; bb < 4; bb++) {
                F2U xp;  // {x,x} duplicated: one LDS.64
                xp.f = *(const float2*)&sx2[k * PAD2 + (ty * 4 + bb) * 2];

                // pair 0: acc += (t*wo) * (1 + tt*(c3 + c5*tt))
                ull t0 = fma2_(xp.u, ws.u.lo, bs.u.lo);
                ull s0 = mul2_(t0, t0);
                ull p0 = fma2_(C5, s0, C3);
                ull h0 = fma2_(p0, s0, ONE);
                ull u0 = mul2_(t0, wo.u.lo);
                acc[bb][0] = fma2_(u0, h0, acc[bb][0]);

                // pair 1
                ull t1 = fma2_(xp.u, ws.u.hi, bs.u.hi);
                ull s1 = mul2_(t1, t1);
                ull p1 = fma2_(C5, s1, C3);
                ull h1 = fma2_(p1, s1, ONE);
                ull u1 = mul2_(t1, wo.u.hi);
                acc[bb][1] = fma2_(u1, h1, acc[bb][1]);
            }
        }

        __syncthreads();
        if (k0 + BK < IN_DIM) {
            #pragma unroll
            for (int j = 0; j < 8; j++) {
                int idx = tid + j * 256;
                int r = idx >> 5, k = idx & 31;
                *(float2*)&sx2[k * PAD2 + r * 2] = make_float2(rx[j], rx[j]);
                swo[k * PAD + r] = rw[j].x;
                sws[k * PAD + r] = rw[j].y;
                sbs[k * PAD + r] = rb[j];
            }
            __syncthreads();
        }
    }

    // ---- epilogue ----
    float bo[4];
    #pragma unroll
    for (int oo = 0; oo < 4; oo++)
        bo[oo] = bias[(oCol + tx * 4 + oo) * (IN_DIM + 1) + IN_DIM];

    #pragma unroll
    for (int bb = 0; bb < 4; bb++) {
        F2U p0; p0.u = acc[bb][0];
        F2U p1; p1.u = acc[bb][1];
        float4 v;
        v.x = p0.f.x + bo[0];
        v.y = p0.f.y + bo[1];
        v.z = p1.f.x + bo[2];
        v.w = p1.f.y + bo[3];
        *(float4*)&out[(bRow + ty * 4 + bb) * OUT_DIM + oCol + tx * 4] = v;
    }
}

extern "C" void kernel_launch(void* const* d_in, const int* in_sizes, int n_in,
                              void* d_out, int out_size) {
    const float* x      = (const float*)d_in[0];
    const float* weight = (const float*)d_in[1];
    const float* bias   = (const float*)d_in[2];
    float* out          = (float*)d_out;

    dim3 grid(OUT_DIM / BN, B_DIM / BM);  // (8, 16) = 128 CTAs
    trigo_kernel<<<grid, 256>>>(x, weight, bias, out);
}